// round 7
// baseline (speedup 1.0000x reference)
#include <cuda_runtime.h>

#define TP 94
#define NN 128
#define HH 32

__device__ float g_h[TP * NN * HH];

// ---------------------------------------------------------------------------
// Kernel 1: conv stack. One block per n, 1024 threads: q = tid>>7 (0..7)
// splits output channels (2/4/4 oc per thread per stage) -> 8 warps/SMSP.
// ---------------------------------------------------------------------------
__global__ void __launch_bounds__(1024) conv_kernel(
    const float* __restrict__ x,
    const float* __restrict__ w1, const float* __restrict__ b1,
    const float* __restrict__ w2, const float* __restrict__ b2,
    const float* __restrict__ w3, const float* __restrict__ b3)
{
    __shared__ float x_s[400];
    __shared__ float w1_s[192], b1_s[16];
    __shared__ float w2_s[1536], b2_s[32];
    __shared__ float w3_s[3072], b3_s[32];
    __shared__ float h1_s[98 * 17];
    __shared__ float h2_s[96 * 33];

    const int n = blockIdx.x;
    const int tid = threadIdx.x;
    const int t = tid & 127;
    const int q = tid >> 7;          // 0..7

    for (int idx = tid; idx < 400;  idx += 1024) x_s[idx]  = x[n * 400 + idx];
    for (int idx = tid; idx < 192;  idx += 1024) w1_s[idx] = w1[idx];
    for (int idx = tid; idx < 1536; idx += 1024) w2_s[idx] = w2[idx];
    for (int idx = tid; idx < 3072; idx += 1024) w3_s[idx] = w3[idx];
    if (tid < 16) b1_s[tid] = b1[tid];
    if (tid < 32) { b2_s[tid] = b2[tid]; b3_s[tid] = b3[tid]; }
    __syncthreads();

    // Stage 1: conv1 4->16, T 100->98.  2 oc per thread.
    if (t < 98) {
        float xv[12];
        #pragma unroll
        for (int k = 0; k < 3; k++)
            #pragma unroll
            for (int i = 0; i < 4; i++)
                xv[k * 4 + i] = x_s[(t + k) * 4 + i];
        const int oc0 = q * 2;
        #pragma unroll
        for (int o = 0; o < 2; o++) {
            int oc = oc0 + o;
            float acc = b1_s[oc];
            #pragma unroll
            for (int i = 0; i < 4; i++)
                #pragma unroll
                for (int k = 0; k < 3; k++)
                    acc += xv[k * 4 + i] * w1_s[(oc * 4 + i) * 3 + k];
            h1_s[t * 17 + oc] = fmaxf(acc, 0.f);
        }
    }
    __syncthreads();

    // Stage 2: conv2 16->32, T 98->96.  4 oc per thread.
    if (t < 96) {
        const int oc0 = q * 4;
        float acc[4];
        #pragma unroll
        for (int o = 0; o < 4; o++) acc[o] = b2_s[oc0 + o];
        for (int ic = 0; ic < 16; ic++) {
            float h0 = h1_s[(t + 0) * 17 + ic];
            float h1v = h1_s[(t + 1) * 17 + ic];
            float h2v = h1_s[(t + 2) * 17 + ic];
            #pragma unroll
            for (int o = 0; o < 4; o++) {
                const float* w = &w2_s[((oc0 + o) * 16 + ic) * 3];
                acc[o] += h0 * w[0] + h1v * w[1] + h2v * w[2];
            }
        }
        #pragma unroll
        for (int o = 0; o < 4; o++)
            h2_s[t * 33 + oc0 + o] = fmaxf(acc[o], 0.f);
    }
    __syncthreads();

    // Stage 3: conv3 32->32, T 96->94.  4 oc per thread.
    if (t < 94) {
        const int oc0 = q * 4;
        float acc[4];
        #pragma unroll
        for (int o = 0; o < 4; o++) acc[o] = b3_s[oc0 + o];
        for (int ic = 0; ic < 32; ic++) {
            float h0 = h2_s[(t + 0) * 33 + ic];
            float h1v = h2_s[(t + 1) * 33 + ic];
            float h2v = h2_s[(t + 2) * 33 + ic];
            #pragma unroll
            for (int o = 0; o < 4; o++) {
                const float* w = &w3_s[((oc0 + o) * 32 + ic) * 3];
                acc[o] += h0 * w[0] + h1v * w[1] + h2v * w[2];
            }
        }
        #pragma unroll
        for (int o = 0; o < 4; o++)
            g_h[(t * NN + n) * HH + oc0 + o] = fmaxf(acc[o], 0.f);
    }
}

// ---------------------------------------------------------------------------
// Kernel 2: one block per t, 1024 threads (32 warps = 8/SMSP).
// d = tid&31, g = tid>>5 (0..31); each thread handles rows {g, g+32, g+64,
// g+96} (4 rows). P2 uses the abs-identity (2 ops/elem).
// ---------------------------------------------------------------------------
__global__ void __launch_bounds__(1024) swarm_kernel(
    const float* __restrict__ x,
    const float* __restrict__ We, const float* __restrict__ be,
    const float* __restrict__ Wa, const float* __restrict__ ba,
    const float* __restrict__ Wu, const float* __restrict__ bu,
    const float* __restrict__ Wd, const float* __restrict__ bd,
    float* __restrict__ out)
{
    extern __shared__ float s[];
    float* h_s  = s;           // 128*33 = 4224
    float* ejT  = s + 4224;    // 32*132 = 4224
    float* ci_s = s + 8448;    // 128*32 = 4096
    float* agA  = s + 12544;   // 128*33 = 4224
    float* agB  = s + 16768;   // 128*33 = 4224
    float* upd  = s + 20992;   // 128*33 = 4224
    float* We_s = s + 25216;   // 2048
    float* be_s = s + 27264;   // 32
    float* Wa_s = s + 27296;   // 1024
    float* ba_s = s + 28320;   // 32
    float* Wu_s = s + 28352;   // 2048
    float* bu_s = s + 30400;   // 32
    float* Wd_s = s + 30432;   // 128
    float* bd_s = s + 30560;   // 4
    // total 30564 floats = 122256 B

    const int t = blockIdx.x;
    const int tid = threadIdx.x;
    const int d = tid & 31;
    const int g = tid >> 5;      // 0..31

    for (int idx = tid; idx < 4096; idx += 1024) {
        int i = idx >> 5, c = idx & 31;
        h_s[i * 33 + c] = g_h[t * 4096 + idx];
    }
    if (tid < 512) {
        for (int idx = tid; idx < 2048; idx += 512) We_s[idx] = We[idx];
    } else {
        int tt = tid - 512;
        for (int idx = tt; idx < 2048; idx += 512) Wu_s[idx] = Wu[idx];
    }
    for (int idx = tid; idx < 1024; idx += 1024) Wa_s[idx] = Wa[idx];
    if (tid < 32) { be_s[tid] = be[tid]; ba_s[tid] = ba[tid]; bu_s[tid] = bu[tid]; }
    else if (tid >= 64 && tid < 192) Wd_s[tid - 64] = Wd[tid - 64];
    else if (tid >= 192 && tid < 196) bd_s[tid - 192] = bd[tid - 192];
    __syncthreads();

    // P1: ejT[d][j] and ci[j][d] = ei + be.  4 j per thread; We loads hoisted.
    {
        float aej[4], aei[4];
        float bev = be_s[d];
        #pragma unroll
        for (int ii = 0; ii < 4; ii++) { aej[ii] = 0.f; aei[ii] = bev; }
        #pragma unroll
        for (int c = 0; c < 32; c++) {
            float wj = We_s[c * 32 + d];
            float wi = We_s[(32 + c) * 32 + d];
            #pragma unroll
            for (int ii = 0; ii < 4; ii++) {
                float hv = h_s[(g + 32 * ii) * 33 + c];   // warp broadcast
                aej[ii] += hv * wj;
                aei[ii] += hv * wi;
            }
        }
        #pragma unroll
        for (int ii = 0; ii < 4; ii++) {
            int j = g + 32 * ii;
            ejT[d * 132 + j] = aej[ii];
            ci_s[j * 32 + d] = aei[ii];
        }
    }
    __syncthreads();

    // P2: agg0[i][d] = 0.5*(S_d + 128*c_i + Sum_j |ej_j + c_i|) - relu(ej_i + c_i)
    {
        float acc[4], cc[4];
        #pragma unroll
        for (int ii = 0; ii < 4; ii++) {
            cc[ii] = ci_s[(g + 32 * ii) * 32 + d];
            acc[ii] = 0.f;
        }
        float S = 0.f;
        const float4* row = (const float4*)&ejT[d * 132];
        #pragma unroll 8
        for (int j4 = 0; j4 < 32; j4++) {
            float4 v = row[j4];
            S += (v.x + v.y) + (v.z + v.w);
            #pragma unroll
            for (int ii = 0; ii < 4; ii++) {
                acc[ii] += fabsf(v.x + cc[ii]);
                acc[ii] += fabsf(v.y + cc[ii]);
                acc[ii] += fabsf(v.z + cc[ii]);
                acc[ii] += fabsf(v.w + cc[ii]);
            }
        }
        #pragma unroll
        for (int ii = 0; ii < 4; ii++) {
            int i = g + 32 * ii;
            float diag = fmaxf(ejT[d * 132 + i] + cc[ii], 0.f);
            agA[i * 33 + d] = 0.5f * (S + 128.f * cc[ii] + acc[ii]) - diag;
        }
    }
    __syncthreads();

    // P3: agg = relu(agg0 @ Wa + ba)
    {
        float acc[4];
        float bav = ba_s[d];
        #pragma unroll
        for (int ii = 0; ii < 4; ii++) acc[ii] = bav;
        #pragma unroll
        for (int c = 0; c < 32; c++) {
            float w = Wa_s[c * 32 + d];
            #pragma unroll
            for (int ii = 0; ii < 4; ii++)
                acc[ii] += agA[(g + 32 * ii) * 33 + c] * w;
        }
        #pragma unroll
        for (int ii = 0; ii < 4; ii++)
            agB[(g + 32 * ii) * 33 + d] = fmaxf(acc[ii], 0.f);
    }
    __syncthreads();

    // P4: upd = relu(h @ Wu[:H] + agg @ Wu[H:] + bu)
    {
        float acc[4];
        float buv = bu_s[d];
        #pragma unroll
        for (int ii = 0; ii < 4; ii++) acc[ii] = buv;
        #pragma unroll
        for (int c = 0; c < 32; c++) {
            float wh = Wu_s[c * 32 + d];
            float wa = Wu_s[(32 + c) * 32 + d];
            #pragma unroll
            for (int ii = 0; ii < 4; ii++) {
                int r = (g + 32 * ii) * 33 + c;
                acc[ii] += h_s[r] * wh;
                acc[ii] += agB[r] * wa;
            }
        }
        #pragma unroll
        for (int ii = 0; ii < 4; ii++)
            upd[(g + 32 * ii) * 33 + d] = fmaxf(acc[ii], 0.f);
    }
    __syncthreads();

    // P5: dec = upd @ Wd + bd;  out = x[:, 6+t] + dec  (first 512 threads)
    if (tid < 512) {
        int i = tid >> 2, dd = tid & 3;
        float acc = bd_s[dd];
        #pragma unroll
        for (int dc = 0; dc < 32; dc++)
            acc += upd[i * 33 + dc] * Wd_s[dc * 4 + dd];
        out[(i * TP + t) * 4 + dd] = x[(i * 100 + 6 + t) * 4 + dd] + acc;
    }
}

// ---------------------------------------------------------------------------
extern "C" void kernel_launch(void* const* d_in, const int* in_sizes, int n_in,
                              void* d_out, int out_size)
{
    const float* x  = (const float*)d_in[0];
    const float* w1 = (const float*)d_in[1];
    const float* b1 = (const float*)d_in[2];
    const float* w2 = (const float*)d_in[3];
    const float* b2 = (const float*)d_in[4];
    const float* w3 = (const float*)d_in[5];
    const float* b3 = (const float*)d_in[6];
    const float* We = (const float*)d_in[7];
    const float* be = (const float*)d_in[8];
    const float* Wa = (const float*)d_in[9];
    const float* ba = (const float*)d_in[10];
    const float* Wu = (const float*)d_in[11];
    const float* bu = (const float*)d_in[12];
    const float* Wd = (const float*)d_in[13];
    const float* bd = (const float*)d_in[14];
    float* out = (float*)d_out;

    cudaFuncSetAttribute(swarm_kernel,
                         cudaFuncAttributeMaxDynamicSharedMemorySize, 30564 * 4);

    conv_kernel<<<128, 1024>>>(x, w1, b1, w2, b2, w3, b3);
    swarm_kernel<<<94, 1024, 30564 * 4>>>(x, We, be, Wa, ba, Wu, bu, Wd, bd, out);
}

// round 8
// speedup vs baseline: 1.1169x; 1.1169x over previous
#include <cuda_runtime.h>

#define TP 94
#define NN 128
#define HH 32

__device__ float g_h[TP * NN * HH];

// ---------------------------------------------------------------------------
// Kernel 1: conv stack (R5-proven config). One block per n, 512 threads:
// quarter = tid>>7 splits output channels (4/8/8 oc per thread per stage).
// ---------------------------------------------------------------------------
__global__ void __launch_bounds__(512) conv_kernel(
    const float* __restrict__ x,
    const float* __restrict__ w1, const float* __restrict__ b1,
    const float* __restrict__ w2, const float* __restrict__ b2,
    const float* __restrict__ w3, const float* __restrict__ b3)
{
    __shared__ float x_s[400];
    __shared__ float w1_s[192], b1_s[16];
    __shared__ float w2_s[1536], b2_s[32];
    __shared__ float w3_s[3072], b3_s[32];
    __shared__ float h1_s[98 * 17];
    __shared__ float h2_s[96 * 33];

    const int n = blockIdx.x;
    const int tid = threadIdx.x;
    const int t = tid & 127;
    const int q = tid >> 7;          // 0..3

    for (int idx = tid; idx < 400;  idx += 512) x_s[idx]  = x[n * 400 + idx];
    for (int idx = tid; idx < 192;  idx += 512) w1_s[idx] = w1[idx];
    for (int idx = tid; idx < 1536; idx += 512) w2_s[idx] = w2[idx];
    for (int idx = tid; idx < 3072; idx += 512) w3_s[idx] = w3[idx];
    if (tid < 16) b1_s[tid] = b1[tid];
    if (tid < 32) { b2_s[tid] = b2[tid]; b3_s[tid] = b3[tid]; }
    __syncthreads();

    // Stage 1: conv1 4->16, T 100->98.  4 oc per thread.
    if (t < 98) {
        float xv[12];
        #pragma unroll
        for (int k = 0; k < 3; k++)
            #pragma unroll
            for (int i = 0; i < 4; i++)
                xv[k * 4 + i] = x_s[(t + k) * 4 + i];
        const int oc0 = q * 4;
        #pragma unroll
        for (int o = 0; o < 4; o++) {
            int oc = oc0 + o;
            float acc = b1_s[oc];
            #pragma unroll
            for (int i = 0; i < 4; i++)
                #pragma unroll
                for (int k = 0; k < 3; k++)
                    acc += xv[k * 4 + i] * w1_s[(oc * 4 + i) * 3 + k];
            h1_s[t * 17 + oc] = fmaxf(acc, 0.f);
        }
    }
    __syncthreads();

    // Stage 2: conv2 16->32, T 98->96.  8 oc per thread.
    if (t < 96) {
        const int oc0 = q * 8;
        float acc[8];
        #pragma unroll
        for (int o = 0; o < 8; o++) acc[o] = b2_s[oc0 + o];
        for (int ic = 0; ic < 16; ic++) {
            float h0 = h1_s[(t + 0) * 17 + ic];
            float h1v = h1_s[(t + 1) * 17 + ic];
            float h2v = h1_s[(t + 2) * 17 + ic];
            #pragma unroll
            for (int o = 0; o < 8; o++) {
                const float* w = &w2_s[((oc0 + o) * 16 + ic) * 3];
                acc[o] += h0 * w[0] + h1v * w[1] + h2v * w[2];
            }
        }
        #pragma unroll
        for (int o = 0; o < 8; o++)
            h2_s[t * 33 + oc0 + o] = fmaxf(acc[o], 0.f);
    }
    __syncthreads();

    // Stage 3: conv3 32->32, T 96->94.  8 oc per thread.
    if (t < 94) {
        const int oc0 = q * 8;
        float acc[8];
        #pragma unroll
        for (int o = 0; o < 8; o++) acc[o] = b3_s[oc0 + o];
        for (int ic = 0; ic < 32; ic++) {
            float h0 = h2_s[(t + 0) * 33 + ic];
            float h1v = h2_s[(t + 1) * 33 + ic];
            float h2v = h2_s[(t + 2) * 33 + ic];
            #pragma unroll
            for (int o = 0; o < 8; o++) {
                const float* w = &w3_s[((oc0 + o) * 32 + ic) * 3];
                acc[o] += h0 * w[0] + h1v * w[1] + h2v * w[2];
            }
        }
        #pragma unroll
        for (int o = 0; o < 8; o++)
            g_h[(t * NN + n) * HH + oc0 + o] = fmaxf(acc[o], 0.f);
    }
}

// ---------------------------------------------------------------------------
// Kernel 2: one block per t, 1024 threads (8 warps/SMSP).
// d = tid&31, g = tid>>5 (0..31); each thread handles rows {g, g+32, g+64,
// g+96}. We/Wu repacked interleaved [c][d][2] -> single LDS.64 per c in P1/P4.
// ---------------------------------------------------------------------------
__global__ void __launch_bounds__(1024) swarm_kernel(
    const float* __restrict__ x,
    const float* __restrict__ We, const float* __restrict__ be,
    const float* __restrict__ Wa, const float* __restrict__ ba,
    const float* __restrict__ Wu, const float* __restrict__ bu,
    const float* __restrict__ Wd, const float* __restrict__ bd,
    float* __restrict__ out)
{
    extern __shared__ float s[];
    float* h_s  = s;           // 128*33 = 4224
    float* ejT  = s + 4224;    // 32*132 = 4224
    float* ci_s = s + 8448;    // 128*32 = 4096
    float* agA  = s + 12544;   // 128*33 = 4224
    float* agB  = s + 16768;   // 128*33 = 4224
    float* upd  = s + 20992;   // 128*33 = 4224
    float* Wep  = s + 25216;   // 2048  (packed: [c][d][{wj,wi}])
    float* be_s = s + 27264;   // 32
    float* Wa_s = s + 27296;   // 1024
    float* ba_s = s + 28320;   // 32
    float* Wup  = s + 28352;   // 2048  (packed: [c][d][{wh,wa}])
    float* bu_s = s + 30400;   // 32
    float* Wd_s = s + 30432;   // 128
    float* bd_s = s + 30560;   // 4
    // total 30564 floats = 122256 B

    const int t = blockIdx.x;
    const int tid = threadIdx.x;
    const int d = tid & 31;
    const int g = tid >> 5;      // 0..31

    for (int idx = tid; idx < 4096; idx += 1024) {
        int i = idx >> 5, c = idx & 31;
        h_s[i * 33 + c] = g_h[t * 4096 + idx];
    }
    // Packed weight loads: We[c*32+d] (c<32 -> wj slot 0), We[(32+c)*32+d] -> slot 1
    {
        for (int idx = tid; idx < 2048; idx += 1024) {
            float v = We[idx];
            int half = idx >> 10;            // 0: Wj, 1: Wi
            int c = (idx >> 5) & 31;
            int dd = idx & 31;
            Wep[c * 64 + 2 * dd + half] = v;
        }
        for (int idx = tid; idx < 2048; idx += 1024) {
            float v = Wu[idx];
            int half = idx >> 10;            // 0: Wh, 1: Wa-side
            int c = (idx >> 5) & 31;
            int dd = idx & 31;
            Wup[c * 64 + 2 * dd + half] = v;
        }
    }
    for (int idx = tid; idx < 1024; idx += 1024) Wa_s[idx] = Wa[idx];
    if (tid < 32) { be_s[tid] = be[tid]; ba_s[tid] = ba[tid]; bu_s[tid] = bu[tid]; }
    else if (tid >= 64 && tid < 192) Wd_s[tid - 64] = Wd[tid - 64];
    else if (tid >= 192 && tid < 196) bd_s[tid - 192] = bd[tid - 192];
    __syncthreads();

    // P1: ejT[d][j] and ci[j][d] = ei + be.  4 j per thread; packed We loads.
    {
        float aej[4], aei[4];
        float bev = be_s[d];
        #pragma unroll
        for (int ii = 0; ii < 4; ii++) { aej[ii] = 0.f; aei[ii] = bev; }
        #pragma unroll
        for (int c = 0; c < 32; c++) {
            float2 w = *(const float2*)&Wep[c * 64 + 2 * d];   // (wj, wi)
            #pragma unroll
            for (int ii = 0; ii < 4; ii++) {
                float hv = h_s[(g + 32 * ii) * 33 + c];         // warp broadcast
                aej[ii] += hv * w.x;
                aei[ii] += hv * w.y;
            }
        }
        #pragma unroll
        for (int ii = 0; ii < 4; ii++) {
            int j = g + 32 * ii;
            ejT[d * 132 + j] = aej[ii];
            ci_s[j * 32 + d] = aei[ii];
        }
    }
    __syncthreads();

    // P2: agg0[i][d] = 0.5*(S_d + 128*c_i + Sum_j |ej_j + c_i|) - relu(ej_i + c_i)
    {
        float acc[4], cc[4];
        #pragma unroll
        for (int ii = 0; ii < 4; ii++) {
            cc[ii] = ci_s[(g + 32 * ii) * 32 + d];
            acc[ii] = 0.f;
        }
        float S = 0.f;
        const float4* row = (const float4*)&ejT[d * 132];
        #pragma unroll 8
        for (int j4 = 0; j4 < 32; j4++) {
            float4 v = row[j4];
            S += (v.x + v.y) + (v.z + v.w);
            #pragma unroll
            for (int ii = 0; ii < 4; ii++) {
                acc[ii] += fabsf(v.x + cc[ii]);
                acc[ii] += fabsf(v.y + cc[ii]);
                acc[ii] += fabsf(v.z + cc[ii]);
                acc[ii] += fabsf(v.w + cc[ii]);
            }
        }
        #pragma unroll
        for (int ii = 0; ii < 4; ii++) {
            int i = g + 32 * ii;
            float diag = fmaxf(ejT[d * 132 + i] + cc[ii], 0.f);
            agA[i * 33 + d] = 0.5f * (S + 128.f * cc[ii] + acc[ii]) - diag;
        }
    }
    __syncthreads();

    // P3: agg = relu(agg0 @ Wa + ba)
    {
        float acc[4];
        float bav = ba_s[d];
        #pragma unroll
        for (int ii = 0; ii < 4; ii++) acc[ii] = bav;
        #pragma unroll
        for (int c = 0; c < 32; c++) {
            float w = Wa_s[c * 32 + d];
            #pragma unroll
            for (int ii = 0; ii < 4; ii++)
                acc[ii] += agA[(g + 32 * ii) * 33 + c] * w;
        }
        #pragma unroll
        for (int ii = 0; ii < 4; ii++)
            agB[(g + 32 * ii) * 33 + d] = fmaxf(acc[ii], 0.f);
    }
    __syncthreads();

    // P4: upd = relu(h @ Wu[:H] + agg @ Wu[H:] + bu), packed Wu loads
    {
        float acc[4];
        float buv = bu_s[d];
        #pragma unroll
        for (int ii = 0; ii < 4; ii++) acc[ii] = buv;
        #pragma unroll
        for (int c = 0; c < 32; c++) {
            float2 w = *(const float2*)&Wup[c * 64 + 2 * d];   // (wh, wa)
            #pragma unroll
            for (int ii = 0; ii < 4; ii++) {
                int r = (g + 32 * ii) * 33 + c;
                acc[ii] += h_s[r] * w.x;
                acc[ii] += agB[r] * w.y;
            }
        }
        #pragma unroll
        for (int ii = 0; ii < 4; ii++)
            upd[(g + 32 * ii) * 33 + d] = fmaxf(acc[ii], 0.f);
    }
    __syncthreads();

    // P5: dec = upd @ Wd + bd;  out = x[:, 6+t] + dec  (first 512 threads)
    if (tid < 512) {
        int i = tid >> 2, dd = tid & 3;
        float acc = bd_s[dd];
        #pragma unroll
        for (int dc = 0; dc < 32; dc++)
            acc += upd[i * 33 + dc] * Wd_s[dc * 4 + dd];
        out[(i * TP + t) * 4 + dd] = x[(i * 100 + 6 + t) * 4 + dd] + acc;
    }
}

// ---------------------------------------------------------------------------
extern "C" void kernel_launch(void* const* d_in, const int* in_sizes, int n_in,
                              void* d_out, int out_size)
{
    const float* x  = (const float*)d_in[0];
    const float* w1 = (const float*)d_in[1];
    const float* b1 = (const float*)d_in[2];
    const float* w2 = (const float*)d_in[3];
    const float* b2 = (const float*)d_in[4];
    const float* w3 = (const float*)d_in[5];
    const float* b3 = (const float*)d_in[6];
    const float* We = (const float*)d_in[7];
    const float* be = (const float*)d_in[8];
    const float* Wa = (const float*)d_in[9];
    const float* ba = (const float*)d_in[10];
    const float* Wu = (const float*)d_in[11];
    const float* bu = (const float*)d_in[12];
    const float* Wd = (const float*)d_in[13];
    const float* bd = (const float*)d_in[14];
    float* out = (float*)d_out;

    cudaFuncSetAttribute(swarm_kernel,
                         cudaFuncAttributeMaxDynamicSharedMemorySize, 30564 * 4);

    conv_kernel<<<128, 512>>>(x, w1, b1, w2, b2, w3, b3);
    swarm_kernel<<<94, 1024, 30564 * 4>>>(x, We, be, Wa, ba, Wu, bu, Wd, bd, out);
}

// round 9
// speedup vs baseline: 1.1288x; 1.0107x over previous
#include <cuda_runtime.h>

#define TP 94
#define NN 128
#define HH 32

__device__ float g_h[TP * NN * HH];

// ---------------------------------------------------------------------------
// Kernel 1: conv stack (R5-proven config). One block per n, 512 threads:
// quarter = tid>>7 splits output channels (4/8/8 oc per thread per stage).
// ---------------------------------------------------------------------------
__global__ void __launch_bounds__(512) conv_kernel(
    const float* __restrict__ x,
    const float* __restrict__ w1, const float* __restrict__ b1,
    const float* __restrict__ w2, const float* __restrict__ b2,
    const float* __restrict__ w3, const float* __restrict__ b3)
{
    __shared__ float x_s[400];
    __shared__ float w1_s[192], b1_s[16];
    __shared__ float w2_s[1536], b2_s[32];
    __shared__ float w3_s[3072], b3_s[32];
    __shared__ float h1_s[98 * 17];
    __shared__ float h2_s[96 * 33];

    const int n = blockIdx.x;
    const int tid = threadIdx.x;
    const int t = tid & 127;
    const int q = tid >> 7;          // 0..3

    for (int idx = tid; idx < 400;  idx += 512) x_s[idx]  = x[n * 400 + idx];
    for (int idx = tid; idx < 192;  idx += 512) w1_s[idx] = w1[idx];
    for (int idx = tid; idx < 1536; idx += 512) w2_s[idx] = w2[idx];
    for (int idx = tid; idx < 3072; idx += 512) w3_s[idx] = w3[idx];
    if (tid < 16) b1_s[tid] = b1[tid];
    if (tid < 32) { b2_s[tid] = b2[tid]; b3_s[tid] = b3[tid]; }
    __syncthreads();

    if (t < 98) {
        float xv[12];
        #pragma unroll
        for (int k = 0; k < 3; k++)
            #pragma unroll
            for (int i = 0; i < 4; i++)
                xv[k * 4 + i] = x_s[(t + k) * 4 + i];
        const int oc0 = q * 4;
        #pragma unroll
        for (int o = 0; o < 4; o++) {
            int oc = oc0 + o;
            float acc = b1_s[oc];
            #pragma unroll
            for (int i = 0; i < 4; i++)
                #pragma unroll
                for (int k = 0; k < 3; k++)
                    acc += xv[k * 4 + i] * w1_s[(oc * 4 + i) * 3 + k];
            h1_s[t * 17 + oc] = fmaxf(acc, 0.f);
        }
    }
    __syncthreads();

    if (t < 96) {
        const int oc0 = q * 8;
        float acc[8];
        #pragma unroll
        for (int o = 0; o < 8; o++) acc[o] = b2_s[oc0 + o];
        for (int ic = 0; ic < 16; ic++) {
            float h0 = h1_s[(t + 0) * 17 + ic];
            float h1v = h1_s[(t + 1) * 17 + ic];
            float h2v = h1_s[(t + 2) * 17 + ic];
            #pragma unroll
            for (int o = 0; o < 8; o++) {
                const float* w = &w2_s[((oc0 + o) * 16 + ic) * 3];
                acc[o] += h0 * w[0] + h1v * w[1] + h2v * w[2];
            }
        }
        #pragma unroll
        for (int o = 0; o < 8; o++)
            h2_s[t * 33 + oc0 + o] = fmaxf(acc[o], 0.f);
    }
    __syncthreads();

    if (t < 94) {
        const int oc0 = q * 8;
        float acc[8];
        #pragma unroll
        for (int o = 0; o < 8; o++) acc[o] = b3_s[oc0 + o];
        for (int ic = 0; ic < 32; ic++) {
            float h0 = h2_s[(t + 0) * 33 + ic];
            float h1v = h2_s[(t + 1) * 33 + ic];
            float h2v = h2_s[(t + 2) * 33 + ic];
            #pragma unroll
            for (int o = 0; o < 8; o++) {
                const float* w = &w3_s[((oc0 + o) * 32 + ic) * 3];
                acc[o] += h0 * w[0] + h1v * w[1] + h2v * w[2];
            }
        }
        #pragma unroll
        for (int o = 0; o < 8; o++)
            g_h[(t * NN + n) * HH + oc0 + o] = fmaxf(acc[o], 0.f);
    }
}

// Bitonic helpers (element id e = r*32 + lane, 128 elems per warp)
#define SHSTEP(v, j, asc) { \
    float p_ = __shfl_xor_sync(0xffffffffu, (v), (j)); \
    bool km_ = (((l & (j)) == 0) == (asc)); \
    (v) = km_ ? fminf((v), p_) : fmaxf((v), p_); }

#define CASR(a, b, asc) { \
    float mn_ = fminf((a), (b)), mx_ = fmaxf((a), (b)); \
    (a) = (asc) ? mn_ : mx_; (b) = (asc) ? mx_ : mn_; }

// ---------------------------------------------------------------------------
// Kernel 2: one block per t, 1024 threads.  P2 now O(N log N):
// per-d sort (bitonic, warp-local) + prefix sums + binary-search queries.
// ---------------------------------------------------------------------------
__global__ void __launch_bounds__(1024) swarm_kernel(
    const float* __restrict__ x,
    const float* __restrict__ We, const float* __restrict__ be,
    const float* __restrict__ Wa, const float* __restrict__ ba,
    const float* __restrict__ Wu, const float* __restrict__ bu,
    const float* __restrict__ Wd, const float* __restrict__ bd,
    float* __restrict__ out)
{
    extern __shared__ float s[];
    float* h_s  = s;           // 128*33 = 4224
    float* ejT  = s + 4224;    // 32*132 = 4224
    float* ci_s = s + 8448;    // 128*32 = 4096
    float* agA  = s + 12544;   // 128*33 = 4224
    float* agB  = s + 16768;   // 128*33 = 4224  (P2: prefix table; P3: agg)
    float* upd  = s + 20992;   // 128*33 = 4224  (P2: sorted rows; P4: upd)
    float* Wep  = s + 25216;   // 2048  (packed [c][d][{wj,wi}])
    float* be_s = s + 27264;   // 32
    float* Wa_s = s + 27296;   // 1024
    float* ba_s = s + 28320;   // 32
    float* Wup  = s + 28352;   // 2048  (packed [c][d][{wh,wa}])
    float* bu_s = s + 30400;   // 32
    float* Wd_s = s + 30432;   // 128
    float* bd_s = s + 30560;   // 4
    // total 30564 floats = 122256 B

    const int t = blockIdx.x;
    const int tid = threadIdx.x;
    const int d = tid & 31;
    const int g = tid >> 5;      // 0..31

    for (int idx = tid; idx < 4096; idx += 1024) {
        int i = idx >> 5, c = idx & 31;
        h_s[i * 33 + c] = g_h[t * 4096 + idx];
    }
    for (int idx = tid; idx < 2048; idx += 1024) {
        float v = We[idx];
        int half = idx >> 10;
        int c = (idx >> 5) & 31;
        int dd = idx & 31;
        Wep[c * 64 + 2 * dd + half] = v;
    }
    for (int idx = tid; idx < 2048; idx += 1024) {
        float v = Wu[idx];
        int half = idx >> 10;
        int c = (idx >> 5) & 31;
        int dd = idx & 31;
        Wup[c * 64 + 2 * dd + half] = v;
    }
    for (int idx = tid; idx < 1024; idx += 1024) Wa_s[idx] = Wa[idx];
    if (tid < 32) { be_s[tid] = be[tid]; ba_s[tid] = ba[tid]; bu_s[tid] = bu[tid]; }
    else if (tid >= 64 && tid < 192) Wd_s[tid - 64] = Wd[tid - 64];
    else if (tid >= 192 && tid < 196) bd_s[tid - 192] = bd[tid - 192];
    __syncthreads();

    // P1: ejT[d][j] and ci[j][d] = ei + be.  4 j per thread; packed We loads.
    {
        float aej[4], aei[4];
        float bev = be_s[d];
        #pragma unroll
        for (int ii = 0; ii < 4; ii++) { aej[ii] = 0.f; aei[ii] = bev; }
        #pragma unroll
        for (int c = 0; c < 32; c++) {
            float2 w = *(const float2*)&Wep[c * 64 + 2 * d];   // (wj, wi)
            #pragma unroll
            for (int ii = 0; ii < 4; ii++) {
                float hv = h_s[(g + 32 * ii) * 33 + c];
                aej[ii] += hv * w.x;
                aei[ii] += hv * w.y;
            }
        }
        #pragma unroll
        for (int ii = 0; ii < 4; ii++) {
            int j = g + 32 * ii;
            ejT[d * 132 + j] = aej[ii];
            ci_s[j * 32 + d] = aei[ii];
        }
    }
    __syncthreads();

    // P2a: warp w sorts ejT row (d = w) ascending + exclusive prefix sums.
    //      sorted -> upd region (stride 132), prefix -> agB region (129 used).
    {
        const int w = g;
        const int l = d;
        float v0 = ejT[w * 132 +  0 + l];
        float v1 = ejT[w * 132 + 32 + l];
        float v2 = ejT[w * 132 + 64 + l];
        float v3 = ejT[w * 132 + 96 + l];

        // k=2
        { bool a = ((l & 2) == 0);
          SHSTEP(v0,1,a) SHSTEP(v1,1,a) SHSTEP(v2,1,a) SHSTEP(v3,1,a) }
        // k=4
        { bool a = ((l & 4) == 0);
          SHSTEP(v0,2,a) SHSTEP(v1,2,a) SHSTEP(v2,2,a) SHSTEP(v3,2,a)
          SHSTEP(v0,1,a) SHSTEP(v1,1,a) SHSTEP(v2,1,a) SHSTEP(v3,1,a) }
        // k=8
        { bool a = ((l & 8) == 0);
          SHSTEP(v0,4,a) SHSTEP(v1,4,a) SHSTEP(v2,4,a) SHSTEP(v3,4,a)
          SHSTEP(v0,2,a) SHSTEP(v1,2,a) SHSTEP(v2,2,a) SHSTEP(v3,2,a)
          SHSTEP(v0,1,a) SHSTEP(v1,1,a) SHSTEP(v2,1,a) SHSTEP(v3,1,a) }
        // k=16
        { bool a = ((l & 16) == 0);
          SHSTEP(v0,8,a) SHSTEP(v1,8,a) SHSTEP(v2,8,a) SHSTEP(v3,8,a)
          SHSTEP(v0,4,a) SHSTEP(v1,4,a) SHSTEP(v2,4,a) SHSTEP(v3,4,a)
          SHSTEP(v0,2,a) SHSTEP(v1,2,a) SHSTEP(v2,2,a) SHSTEP(v3,2,a)
          SHSTEP(v0,1,a) SHSTEP(v1,1,a) SHSTEP(v2,1,a) SHSTEP(v3,1,a) }
        // k=32: asc by (r&1)==0 -> r0,r2 asc; r1,r3 desc.  j=16..1 (shuffles)
        #pragma unroll
        for (int j = 16; j >= 1; j >>= 1) {
            SHSTEP(v0,j,true) SHSTEP(v1,j,false) SHSTEP(v2,j,true) SHSTEP(v3,j,false)
        }
        // k=64: asc by (r&2)==0 -> r0,r1 asc; r2,r3 desc.
        CASR(v0, v1, true)
        CASR(v2, v3, false)
        #pragma unroll
        for (int j = 16; j >= 1; j >>= 1) {
            SHSTEP(v0,j,true) SHSTEP(v1,j,true) SHSTEP(v2,j,false) SHSTEP(v3,j,false)
        }
        // k=128: all ascending
        CASR(v0, v2, true)
        CASR(v1, v3, true)
        CASR(v0, v1, true)
        CASR(v2, v3, true)
        #pragma unroll
        for (int j = 16; j >= 1; j >>= 1) {
            SHSTEP(v0,j,true) SHSTEP(v1,j,true) SHSTEP(v2,j,true) SHSTEP(v3,j,true)
        }

        // inclusive warp scans per register row
        float i0 = v0, i1 = v1, i2 = v2, i3 = v3;
        #pragma unroll
        for (int o = 1; o < 32; o <<= 1) {
            float s0 = __shfl_up_sync(0xffffffffu, i0, o); if (l >= o) i0 += s0;
            float s1 = __shfl_up_sync(0xffffffffu, i1, o); if (l >= o) i1 += s1;
            float s2 = __shfl_up_sync(0xffffffffu, i2, o); if (l >= o) i2 += s2;
            float s3 = __shfl_up_sync(0xffffffffu, i3, o); if (l >= o) i3 += s3;
        }
        float t0 = __shfl_sync(0xffffffffu, i0, 31);
        float t1 = __shfl_sync(0xffffffffu, i1, 31);
        float t2 = __shfl_sync(0xffffffffu, i2, 31);
        float t3 = __shfl_sync(0xffffffffu, i3, 31);
        float b1v = t0, b2v = t0 + t1, b3v = t0 + t1 + t2;

        upd[w * 132 +  0 + l] = v0;  agB[w * 132 +  0 + l] = i0 - v0;
        upd[w * 132 + 32 + l] = v1;  agB[w * 132 + 32 + l] = i1 - v1 + b1v;
        upd[w * 132 + 64 + l] = v2;  agB[w * 132 + 64 + l] = i2 - v2 + b2v;
        upd[w * 132 + 96 + l] = v3;  agB[w * 132 + 96 + l] = i3 - v3 + b3v;
        if (l == 31) agB[w * 132 + 128] = b3v + t3;   // S_total
    }
    __syncthreads();

    // P2b: queries.  agg0[i][d] = (S - pre[m]) + (128-m)*c - relu(ej_i + c)
    //      where m = #elements <= -c in sorted row d.
    {
        const float* row = &upd[d * 132];
        const float* pre = &agB[d * 132];
        float cc[4];
        #pragma unroll
        for (int ii = 0; ii < 4; ii++)
            cc[ii] = ci_s[(g + 32 * ii) * 32 + d];
        float q0 = -cc[0], q1 = -cc[1], q2 = -cc[2], q3 = -cc[3];
        int m0 = 0, m1 = 0, m2 = 0, m3 = 0;
        #pragma unroll
        for (int st = 64; st >= 1; st >>= 1) {
            if (row[m0 + st - 1] <= q0) m0 += st;
            if (row[m1 + st - 1] <= q1) m1 += st;
            if (row[m2 + st - 1] <= q2) m2 += st;
            if (row[m3 + st - 1] <= q3) m3 += st;
        }
        if (row[m0] <= q0) m0++;
        if (row[m1] <= q1) m1++;
        if (row[m2] <= q2) m2++;
        if (row[m3] <= q3) m3++;
        float Stot = pre[128];
        int mm[4] = {m0, m1, m2, m3};
        #pragma unroll
        for (int ii = 0; ii < 4; ii++) {
            int i = g + 32 * ii;
            float sum = (Stot - pre[mm[ii]]) + (float)(128 - mm[ii]) * cc[ii];
            float diag = fmaxf(ejT[d * 132 + i] + cc[ii], 0.f);
            agA[i * 33 + d] = sum - diag;
        }
    }
    __syncthreads();

    // P3: agg = relu(agg0 @ Wa + ba)   (overwrites the prefix table region)
    {
        float acc[4];
        float bav = ba_s[d];
        #pragma unroll
        for (int ii = 0; ii < 4; ii++) acc[ii] = bav;
        #pragma unroll
        for (int c = 0; c < 32; c++) {
            float w = Wa_s[c * 32 + d];
            #pragma unroll
            for (int ii = 0; ii < 4; ii++)
                acc[ii] += agA[(g + 32 * ii) * 33 + c] * w;
        }
        #pragma unroll
        for (int ii = 0; ii < 4; ii++)
            agB[(g + 32 * ii) * 33 + d] = fmaxf(acc[ii], 0.f);
    }
    __syncthreads();

    // P4: upd = relu(h @ Wu[:H] + agg @ Wu[H:] + bu)  (overwrites sorted rows)
    {
        float acc[4];
        float buv = bu_s[d];
        #pragma unroll
        for (int ii = 0; ii < 4; ii++) acc[ii] = buv;
        #pragma unroll
        for (int c = 0; c < 32; c++) {
            float2 w = *(const float2*)&Wup[c * 64 + 2 * d];   // (wh, wa)
            #pragma unroll
            for (int ii = 0; ii < 4; ii++) {
                int r = (g + 32 * ii) * 33 + c;
                acc[ii] += h_s[r] * w.x;
                acc[ii] += agB[r] * w.y;
            }
        }
        #pragma unroll
        for (int ii = 0; ii < 4; ii++)
            upd[(g + 32 * ii) * 33 + d] = fmaxf(acc[ii], 0.f);
    }
    __syncthreads();

    // P5: dec = upd @ Wd + bd;  out = x[:, 6+t] + dec  (first 512 threads)
    if (tid < 512) {
        int i = tid >> 2, dd = tid & 3;
        float acc = bd_s[dd];
        #pragma unroll
        for (int dc = 0; dc < 32; dc++)
            acc += upd[i * 33 + dc] * Wd_s[dc * 4 + dd];
        out[(i * TP + t) * 4 + dd] = x[(i * 100 + 6 + t) * 4 + dd] + acc;
    }
}

// ---------------------------------------------------------------------------
extern "C" void kernel_launch(void* const* d_in, const int* in_sizes, int n_in,
                              void* d_out, int out_size)
{
    const float* x  = (const float*)d_in[0];
    const float* w1 = (const float*)d_in[1];
    const float* b1 = (const float*)d_in[2];
    const float* w2 = (const float*)d_in[3];
    const float* b2 = (const float*)d_in[4];
    const float* w3 = (const float*)d_in[5];
    const float* b3 = (const float*)d_in[6];
    const float* We = (const float*)d_in[7];
    const float* be = (const float*)d_in[8];
    const float* Wa = (const float*)d_in[9];
    const float* ba = (const float*)d_in[10];
    const float* Wu = (const float*)d_in[11];
    const float* bu = (const float*)d_in[12];
    const float* Wd = (const float*)d_in[13];
    const float* bd = (const float*)d_in[14];
    float* out = (float*)d_out;

    cudaFuncSetAttribute(swarm_kernel,
                         cudaFuncAttributeMaxDynamicSharedMemorySize, 30564 * 4);

    conv_kernel<<<128, 512>>>(x, w1, b1, w2, b2, w3, b3);
    swarm_kernel<<<94, 1024, 30564 * 4>>>(x, We, be, Wa, ba, Wu, bu, Wd, bd, out);
}

// round 10
// speedup vs baseline: 1.5088x; 1.3366x over previous
#include <cuda_runtime.h>

#define TP 94
#define NN 128
#define HH 32

__device__ float g_h[TP * NN * HH];

#define C4(v, u) ((u) == 0 ? (v).x : (u) == 1 ? (v).y : (u) == 2 ? (v).z : (v).w)

// ---------------------------------------------------------------------------
// Kernel 1: conv stack. One block per n, 512 threads (t = tid&127, q = tid>>7
// picks the oc chunk). Weights repacked [ic][k][oc] so each (ic,k) needs only
// broadcast LDS.128 loads. h1 stride 20, h2 stride 36 (16B-aligned rows,
// 8-bank phase pattern = conflict-free for LDS.128).
// ---------------------------------------------------------------------------
__global__ void __launch_bounds__(512) conv_kernel(
    const float* __restrict__ x,
    const float* __restrict__ w1, const float* __restrict__ b1,
    const float* __restrict__ w2, const float* __restrict__ b2,
    const float* __restrict__ w3, const float* __restrict__ b3)
{
    __shared__ __align__(16) float x_s[400];
    __shared__ __align__(16) float w1p[192];    // [(i*3+k)*16 + oc]
    __shared__ __align__(16) float b1_s[16];
    __shared__ __align__(16) float w2p[1536];   // [ic*96 + k*32 + oc]
    __shared__ __align__(16) float b2_s[32];
    __shared__ __align__(16) float w3p[3072];   // [ic*96 + k*32 + oc]
    __shared__ __align__(16) float b3_s[32];
    __shared__ __align__(16) float h1_s[98 * 20];
    __shared__ __align__(16) float h2_s[96 * 36];

    const int n = blockIdx.x;
    const int tid = threadIdx.x;
    const int t = tid & 127;
    const int q = tid >> 7;          // 0..3

    for (int idx = tid; idx < 400; idx += 512) x_s[idx] = x[n * 400 + idx];
    for (int idx = tid; idx < 192; idx += 512) {
        int oc = idx / 12, i = (idx % 12) / 3, k = idx % 3;
        w1p[(i * 3 + k) * 16 + oc] = w1[idx];
    }
    for (int idx = tid; idx < 1536; idx += 512) {
        int oc = idx / 48, ic = (idx % 48) / 3, k = idx % 3;
        w2p[ic * 96 + k * 32 + oc] = w2[idx];
    }
    for (int idx = tid; idx < 3072; idx += 512) {
        int oc = idx / 96, ic = (idx % 96) / 3, k = idx % 3;
        w3p[ic * 96 + k * 32 + oc] = w3[idx];
    }
    if (tid < 16) b1_s[tid] = b1[tid];
    if (tid < 32) { b2_s[tid] = b2[tid]; b3_s[tid] = b3[tid]; }
    __syncthreads();

    // Stage 1: conv1 4->16, T 100->98.  4 oc per thread, float4 everywhere.
    if (t < 98) {
        float4 xa = *(const float4*)&x_s[(t + 0) * 4];
        float4 xb = *(const float4*)&x_s[(t + 1) * 4];
        float4 xc = *(const float4*)&x_s[(t + 2) * 4];
        const int oc0 = q * 4;
        float4 acc = *(const float4*)&b1_s[oc0];
        #pragma unroll
        for (int i = 0; i < 4; i++) {
            #pragma unroll
            for (int k = 0; k < 3; k++) {
                float xv = (k == 0) ? C4(xa, i) : (k == 1) ? C4(xb, i) : C4(xc, i);
                float4 wv = *(const float4*)&w1p[(i * 3 + k) * 16 + oc0];
                acc.x += xv * wv.x; acc.y += xv * wv.y;
                acc.z += xv * wv.z; acc.w += xv * wv.w;
            }
        }
        acc.x = fmaxf(acc.x, 0.f); acc.y = fmaxf(acc.y, 0.f);
        acc.z = fmaxf(acc.z, 0.f); acc.w = fmaxf(acc.w, 0.f);
        *(float4*)&h1_s[t * 20 + oc0] = acc;
    }
    __syncthreads();

    // Stage 2: conv2 16->32, T 98->96.  8 oc per thread.
    if (t < 96) {
        const int oc0 = q * 8;
        float acc[8];
        #pragma unroll
        for (int o = 0; o < 8; o++) acc[o] = b2_s[oc0 + o];
        #pragma unroll
        for (int ic4 = 0; ic4 < 4; ic4++) {
            float4 ha = *(const float4*)&h1_s[(t + 0) * 20 + ic4 * 4];
            float4 hb = *(const float4*)&h1_s[(t + 1) * 20 + ic4 * 4];
            float4 hc = *(const float4*)&h1_s[(t + 2) * 20 + ic4 * 4];
            #pragma unroll
            for (int u = 0; u < 4; u++) {
                int ic = ic4 * 4 + u;
                #pragma unroll
                for (int k = 0; k < 3; k++) {
                    float hk = (k == 0) ? C4(ha, u) : (k == 1) ? C4(hb, u) : C4(hc, u);
                    float4 wa = *(const float4*)&w2p[ic * 96 + k * 32 + oc0];
                    float4 wb = *(const float4*)&w2p[ic * 96 + k * 32 + oc0 + 4];
                    acc[0] += hk * wa.x; acc[1] += hk * wa.y;
                    acc[2] += hk * wa.z; acc[3] += hk * wa.w;
                    acc[4] += hk * wb.x; acc[5] += hk * wb.y;
                    acc[6] += hk * wb.z; acc[7] += hk * wb.w;
                }
            }
        }
        float4 oa = make_float4(fmaxf(acc[0],0.f), fmaxf(acc[1],0.f),
                                fmaxf(acc[2],0.f), fmaxf(acc[3],0.f));
        float4 ob = make_float4(fmaxf(acc[4],0.f), fmaxf(acc[5],0.f),
                                fmaxf(acc[6],0.f), fmaxf(acc[7],0.f));
        *(float4*)&h2_s[t * 36 + oc0] = oa;
        *(float4*)&h2_s[t * 36 + oc0 + 4] = ob;
    }
    __syncthreads();

    // Stage 3: conv3 32->32, T 96->94.  8 oc per thread; STG.128 out.
    if (t < 94) {
        const int oc0 = q * 8;
        float acc[8];
        #pragma unroll
        for (int o = 0; o < 8; o++) acc[o] = b3_s[oc0 + o];
        #pragma unroll
        for (int ic4 = 0; ic4 < 8; ic4++) {
            float4 ha = *(const float4*)&h2_s[(t + 0) * 36 + ic4 * 4];
            float4 hb = *(const float4*)&h2_s[(t + 1) * 36 + ic4 * 4];
            float4 hc = *(const float4*)&h2_s[(t + 2) * 36 + ic4 * 4];
            #pragma unroll
            for (int u = 0; u < 4; u++) {
                int ic = ic4 * 4 + u;
                #pragma unroll
                for (int k = 0; k < 3; k++) {
                    float hk = (k == 0) ? C4(ha, u) : (k == 1) ? C4(hb, u) : C4(hc, u);
                    float4 wa = *(const float4*)&w3p[ic * 96 + k * 32 + oc0];
                    float4 wb = *(const float4*)&w3p[ic * 96 + k * 32 + oc0 + 4];
                    acc[0] += hk * wa.x; acc[1] += hk * wa.y;
                    acc[2] += hk * wa.z; acc[3] += hk * wa.w;
                    acc[4] += hk * wb.x; acc[5] += hk * wb.y;
                    acc[6] += hk * wb.z; acc[7] += hk * wb.w;
                }
            }
        }
        float4 oa = make_float4(fmaxf(acc[0],0.f), fmaxf(acc[1],0.f),
                                fmaxf(acc[2],0.f), fmaxf(acc[3],0.f));
        float4 ob = make_float4(fmaxf(acc[4],0.f), fmaxf(acc[5],0.f),
                                fmaxf(acc[6],0.f), fmaxf(acc[7],0.f));
        *(float4*)&g_h[(t * NN + n) * HH + oc0] = oa;
        *(float4*)&g_h[(t * NN + n) * HH + oc0 + 4] = ob;
    }
}

// ---------------------------------------------------------------------------
// Kernel 2: one block per t, 1024 threads. abs-identity P2 (proven). P1/P3/P4
// use broadcast LDS.128 operand loads with row-inner loops (bounded liveness).
// Row strides 36 (16B-aligned).
// ---------------------------------------------------------------------------
__global__ void __launch_bounds__(1024) swarm_kernel(
    const float* __restrict__ x,
    const float* __restrict__ We, const float* __restrict__ be,
    const float* __restrict__ Wa, const float* __restrict__ ba,
    const float* __restrict__ Wu, const float* __restrict__ bu,
    const float* __restrict__ Wd, const float* __restrict__ bd,
    float* __restrict__ out)
{
    extern __shared__ float s[];
    float* h_s  = s;            // 128*36 = 4608
    float* ejT  = s + 4608;     // 32*132 = 4224
    float* ci_s = s + 8832;     // 128*32 = 4096
    float* agA  = s + 12928;    // 128*36 = 4608
    float* agB  = s + 17536;    // 128*36 = 4608
    float* upd  = s + 22144;    // 128*36 = 4608
    float* Wep  = s + 26752;    // 2048  (packed [c][d][{wj,wi}])
    float* be_s = s + 28800;    // 32
    float* Wa_s = s + 28832;    // 1024
    float* ba_s = s + 29856;    // 32
    float* Wup  = s + 29888;    // 2048  (packed [c][d][{wh,wa}])
    float* bu_s = s + 31936;    // 32
    float* Wd_s = s + 31968;    // 128
    float* bd_s = s + 32096;    // 4
    // total 32100 floats = 128400 B

    const int t = blockIdx.x;
    const int tid = threadIdx.x;
    const int d = tid & 31;
    const int g = tid >> 5;      // 0..31

    // h ingest: one LDG.128 + STS.128 per thread
    {
        int idx = tid * 4;
        int i = idx >> 5, c = idx & 31;
        float4 v = *(const float4*)&g_h[t * 4096 + idx];
        *(float4*)&h_s[i * 36 + c] = v;
    }
    for (int idx = tid; idx < 2048; idx += 1024) {
        float v = We[idx];
        int half = idx >> 10;
        int c = (idx >> 5) & 31;
        int dd = idx & 31;
        Wep[c * 64 + 2 * dd + half] = v;
    }
    for (int idx = tid; idx < 2048; idx += 1024) {
        float v = Wu[idx];
        int half = idx >> 10;
        int c = (idx >> 5) & 31;
        int dd = idx & 31;
        Wup[c * 64 + 2 * dd + half] = v;
    }
    for (int idx = tid; idx < 1024; idx += 1024) Wa_s[idx] = Wa[idx];
    if (tid < 32) { be_s[tid] = be[tid]; ba_s[tid] = ba[tid]; bu_s[tid] = bu[tid]; }
    else if (tid >= 64 && tid < 192) Wd_s[tid - 64] = Wd[tid - 64];
    else if (tid >= 192 && tid < 196) bd_s[tid - 192] = bd[tid - 192];
    __syncthreads();

    // P1: ejT[d][j] and ci[j][d] = ei + be.  4 j per thread.
    {
        float aej[4], aei[4];
        float bev = be_s[d];
        #pragma unroll
        for (int ii = 0; ii < 4; ii++) { aej[ii] = 0.f; aei[ii] = bev; }
        #pragma unroll
        for (int c4 = 0; c4 < 8; c4++) {
            float2 w0 = *(const float2*)&Wep[(4 * c4 + 0) * 64 + 2 * d];
            float2 w1v = *(const float2*)&Wep[(4 * c4 + 1) * 64 + 2 * d];
            float2 w2v = *(const float2*)&Wep[(4 * c4 + 2) * 64 + 2 * d];
            float2 w3v = *(const float2*)&Wep[(4 * c4 + 3) * 64 + 2 * d];
            #pragma unroll
            for (int ii = 0; ii < 4; ii++) {
                float4 hv = *(const float4*)&h_s[(g + 32 * ii) * 36 + 4 * c4];
                aej[ii] += hv.x * w0.x;  aei[ii] += hv.x * w0.y;
                aej[ii] += hv.y * w1v.x; aei[ii] += hv.y * w1v.y;
                aej[ii] += hv.z * w2v.x; aei[ii] += hv.z * w2v.y;
                aej[ii] += hv.w * w3v.x; aei[ii] += hv.w * w3v.y;
            }
        }
        #pragma unroll
        for (int ii = 0; ii < 4; ii++) {
            int j = g + 32 * ii;
            ejT[d * 132 + j] = aej[ii];
            ci_s[j * 32 + d] = aei[ii];
        }
    }
    __syncthreads();

    // P2: agg0[i][d] = 0.5*(S_d + 128*c_i + Sum_j |ej_j + c_i|) - relu(ej_i + c_i)
    {
        float acc[4], cc[4];
        #pragma unroll
        for (int ii = 0; ii < 4; ii++) {
            cc[ii] = ci_s[(g + 32 * ii) * 32 + d];
            acc[ii] = 0.f;
        }
        float S = 0.f;
        const float4* row = (const float4*)&ejT[d * 132];
        #pragma unroll 8
        for (int j4 = 0; j4 < 32; j4++) {
            float4 v = row[j4];
            S += (v.x + v.y) + (v.z + v.w);
            #pragma unroll
            for (int ii = 0; ii < 4; ii++) {
                acc[ii] += fabsf(v.x + cc[ii]);
                acc[ii] += fabsf(v.y + cc[ii]);
                acc[ii] += fabsf(v.z + cc[ii]);
                acc[ii] += fabsf(v.w + cc[ii]);
            }
        }
        #pragma unroll
        for (int ii = 0; ii < 4; ii++) {
            int i = g + 32 * ii;
            float diag = fmaxf(ejT[d * 132 + i] + cc[ii], 0.f);
            agA[i * 36 + d] = 0.5f * (S + 128.f * cc[ii] + acc[ii]) - diag;
        }
    }
    __syncthreads();

    // P3: agg = relu(agg0 @ Wa + ba)
    {
        float acc[4];
        float bav = ba_s[d];
        #pragma unroll
        for (int ii = 0; ii < 4; ii++) acc[ii] = bav;
        #pragma unroll
        for (int c4 = 0; c4 < 8; c4++) {
            float wq0 = Wa_s[(4 * c4 + 0) * 32 + d];
            float wq1 = Wa_s[(4 * c4 + 1) * 32 + d];
            float wq2 = Wa_s[(4 * c4 + 2) * 32 + d];
            float wq3 = Wa_s[(4 * c4 + 3) * 32 + d];
            #pragma unroll
            for (int ii = 0; ii < 4; ii++) {
                float4 av = *(const float4*)&agA[(g + 32 * ii) * 36 + 4 * c4];
                acc[ii] += av.x * wq0 + av.y * wq1 + av.z * wq2 + av.w * wq3;
            }
        }
        #pragma unroll
        for (int ii = 0; ii < 4; ii++)
            agB[(g + 32 * ii) * 36 + d] = fmaxf(acc[ii], 0.f);
    }
    __syncthreads();

    // P4: upd = relu(h @ Wu[:H] + agg @ Wu[H:] + bu)
    {
        float acc[4];
        float buv = bu_s[d];
        #pragma unroll
        for (int ii = 0; ii < 4; ii++) acc[ii] = buv;
        #pragma unroll
        for (int c4 = 0; c4 < 8; c4++) {
            float2 w0 = *(const float2*)&Wup[(4 * c4 + 0) * 64 + 2 * d];
            float2 w1v = *(const float2*)&Wup[(4 * c4 + 1) * 64 + 2 * d];
            float2 w2v = *(const float2*)&Wup[(4 * c4 + 2) * 64 + 2 * d];
            float2 w3v = *(const float2*)&Wup[(4 * c4 + 3) * 64 + 2 * d];
            #pragma unroll
            for (int ii = 0; ii < 4; ii++) {
                int r = (g + 32 * ii) * 36 + 4 * c4;
                float4 hv = *(const float4*)&h_s[r];
                float4 av = *(const float4*)&agB[r];
                acc[ii] += hv.x * w0.x  + av.x * w0.y;
                acc[ii] += hv.y * w1v.x + av.y * w1v.y;
                acc[ii] += hv.z * w2v.x + av.z * w2v.y;
                acc[ii] += hv.w * w3v.x + av.w * w3v.y;
            }
        }
        #pragma unroll
        for (int ii = 0; ii < 4; ii++)
            upd[(g + 32 * ii) * 36 + d] = fmaxf(acc[ii], 0.f);
    }
    __syncthreads();

    // P5: dec = upd @ Wd + bd;  out = x[:, 6+t] + dec  (first 512 threads)
    if (tid < 512) {
        int i = tid >> 2, dd = tid & 3;
        float acc = bd_s[dd];
        #pragma unroll
        for (int dc = 0; dc < 32; dc++)
            acc += upd[i * 36 + dc] * Wd_s[dc * 4 + dd];
        out[(i * TP + t) * 4 + dd] = x[(i * 100 + 6 + t) * 4 + dd] + acc;
    }
}

// ---------------------------------------------------------------------------
extern "C" void kernel_launch(void* const* d_in, const int* in_sizes, int n_in,
                              void* d_out, int out_size)
{
    const float* x  = (const float*)d_in[0];
    const float* w1 = (const float*)d_in[1];
    const float* b1 = (const float*)d_in[2];
    const float* w2 = (const float*)d_in[3];
    const float* b2 = (const float*)d_in[4];
    const float* w3 = (const float*)d_in[5];
    const float* b3 = (const float*)d_in[6];
    const float* We = (const float*)d_in[7];
    const float* be = (const float*)d_in[8];
    const float* Wa = (const float*)d_in[9];
    const float* ba = (const float*)d_in[10];
    const float* Wu = (const float*)d_in[11];
    const float* bu = (const float*)d_in[12];
    const float* Wd = (const float*)d_in[13];
    const float* bd = (const float*)d_in[14];
    float* out = (float*)d_out;

    cudaFuncSetAttribute(swarm_kernel,
                         cudaFuncAttributeMaxDynamicSharedMemorySize, 32100 * 4);

    conv_kernel<<<128, 512>>>(x, w1, b1, w2, b2, w3, b3);
    swarm_kernel<<<94, 1024, 32100 * 4>>>(x, We, be, Wa, ba, Wu, bu, Wd, bd, out);
}